// round 3
// baseline (speedup 1.0000x reference)
#include <cuda_runtime.h>
#include <math.h>

#define NBOX 256
#define BMAX 16

// Mask offsets within the combined mask buffer
#define PLANE0 6400   // 80*80
#define PLANE1 1600   // 40*40
#define PLANE2 400    // 20*20
#define MOFF0 0
#define MOFF1 (16*PLANE0)            // 102400
#define MOFF2 (MOFF1 + 16*PLANE1)    // 128000
#define MTOT  (MOFF2 + 16*PLANE2)    // 134400

// Scratch (allocation-free: __device__ globals)
__device__ __align__(16) float  g_ex[3][NBOX * 80];
__device__ __align__(16) float  g_ey[3][NBOX * 80];
__device__ __align__(16) float  g_mask[MTOT];
__device__ int    g_list[BMAX * NBOX];
__device__ int    g_cnt[BMAX];
__device__ double g_sse[3];
__device__ double g_summ[3];

// ---------------------------------------------------------------------------
__global__ void init_kernel() {
    int i = threadIdx.x;
    if (i < 3) { g_sse[i] = 0.0; g_summ[i] = 0.0; }
}

__global__ void build_lists_kernel(const int* __restrict__ bidx) {
    int b = threadIdx.x;
    if (b >= BMAX) return;
    int c = 0;
    for (int n = 0; n < NBOX; n++)
        if (bidx[n] == b) g_list[b * NBOX + c++] = n;
    g_cnt[b] = c;
}

// Per-box separable gaussian tables. gauss = exp(-tx)*exp(-ty) with
// denom = STD^2*(w/2)^2 = w^2 (STD=2).
__global__ void prep_kernel(const float* __restrict__ bboxes, int S, int level) {
    int n = blockIdx.x;
    int x = threadIdx.x;
    if (x >= S) return;
    float4 bb = reinterpret_cast<const float4*>(bboxes)[n];
    float fS = (float)S;
    int S1 = S - 1;
    int xc = (int)floorf(bb.x * fS);
    int yc = (int)floorf(bb.y * fS);
    int w  = (int)floorf(bb.z * fS);
    int h  = (int)floorf(bb.w * fS);
    int xl = max(xc - w / 2, 0);
    int xr = min(xc + w / 2, S1);
    int yt = max(yc - h / 2, 0);
    int yd = min(yc + h / 2, S1);
    float wd = (float)(xr - xl + 1);
    float ht = (float)(yd - yt + 1);
    float fx = (float)x;
    float dx = fx - (float)xc;
    float dy = fx - (float)yc;
    float tx = (dx * dx) / (wd * wd);
    float ty = (dy * dy) / (ht * ht);
    g_ex[level][n * S + x] = (x >= xl && x <= xr) ? expf(-tx) : 0.0f;
    g_ey[level][n * S + x] = (x >= yt && x <= yd) ? expf(-ty) : 0.0f;
}

// ---------------------------------------------------------------------------
__device__ __forceinline__ float block_reduce_sum(float v) {
    __shared__ float sh[32];
    #pragma unroll
    for (int off = 16; off > 0; off >>= 1)
        v += __shfl_down_sync(0xffffffffu, v, off);
    int lane = threadIdx.x & 31;
    int wid  = threadIdx.x >> 5;
    if (lane == 0) sh[wid] = v;
    __syncthreads();
    int nw = (blockDim.x + 31) >> 5;
    v = (threadIdx.x < nw) ? sh[threadIdx.x] : 0.0f;
    if (wid == 0) {
        #pragma unroll
        for (int off = 16; off > 0; off >>= 1)
            v += __shfl_down_sync(0xffffffffu, v, off);
    }
    return v;  // valid in thread 0
}

// Mask: per-pixel max over boxes of this batch, plus sum(m) accumulation.
__global__ void mask_kernel(int S, int level, int moff) {
    int plane = S * S;
    int i = blockIdx.x * blockDim.x + threadIdx.x;
    float v = 0.0f;
    // grid is exact (total divisible by 256), no bounds guard needed
    int b = i / plane;
    int r = i - b * plane;
    int y = r / S;
    int x = r - y * S;
    int cnt = g_cnt[b];
    const int*   lst = &g_list[b * NBOX];
    const float* ex  = g_ex[level];
    const float* ey  = g_ey[level];
    for (int k = 0; k < cnt; k++) {
        int n = lst[k];
        v = fmaxf(v, ex[n * S + x] * ey[n * S + y]);
    }
    g_mask[moff + i] = v;
    float bs = block_reduce_sum(v);
    if (threadIdx.x == 0) atomicAdd(&g_summ[level], (double)bs);
}

// Main HBM-bound reduction: sum over (b,c,y,x) of (m*(p-t))^2.
// Each thread owns a fixed (b, j4) float4 of the mask (register-resident)
// and loops over a chunk of C channels -> mask read once, p/t streamed.
__global__ void reduce_kernel(const float4* __restrict__ p,
                              const float4* __restrict__ t,
                              int C, int plane4, int cchunk, int level, int moff) {
    const float4* m = reinterpret_cast<const float4*>(&g_mask[moff]);
    int idx = blockIdx.x * blockDim.x + threadIdx.x;
    int nsplit = C / cchunk;
    int per_b = plane4 * nsplit;
    float acc = 0.0f;
    // grid is exact (total divisible by 256)
    int b  = idx / per_b;
    int r  = idx - b * per_b;
    int sp = r / plane4;
    int j  = r - sp * plane4;
    float4 mv = m[b * plane4 + j];
    int base = (b * C + sp * cchunk) * plane4 + j;
    #pragma unroll 4
    for (int c = 0; c < cchunk; c++) {
        float4 pv = p[base];
        float4 tv = t[base];
        base += plane4;
        float d0 = (pv.x - tv.x) * mv.x;
        float d1 = (pv.y - tv.y) * mv.y;
        float d2 = (pv.z - tv.z) * mv.z;
        float d3 = (pv.w - tv.w) * mv.w;
        acc += d0 * d0 + d1 * d1 + d2 * d2 + d3 * d3;
    }
    float bs = block_reduce_sum(acc);
    if (threadIdx.x == 0) atomicAdd(&g_sse[level], (double)bs);
}

__global__ void final_kernel(float* __restrict__ out) {
    const double Cs[3] = {128.0, 256.0, 512.0};
    double tot = 0.0;
    #pragma unroll
    for (int l = 0; l < 3; l++)
        tot += g_sse[l] / (Cs[l] * g_summ[l]);
    out[0] = (float)(tot / 3.0);
}

// ---------------------------------------------------------------------------
extern "C" void kernel_launch(void* const* d_in, const int* in_sizes, int n_in,
                              void* d_out, int out_size) {
    // metadata order (interleaved by setup_inputs loop):
    // 0:y_pred0 1:y_true0 2:y_pred1 3:y_true1 4:y_pred2 5:y_true2
    // 6:bboxes 7:cls 8:batch_idx
    const float* p0 = (const float*)d_in[0];
    const float* t0 = (const float*)d_in[1];
    const float* p1 = (const float*)d_in[2];
    const float* t1 = (const float*)d_in[3];
    const float* p2 = (const float*)d_in[4];
    const float* t2 = (const float*)d_in[5];
    const float* bboxes = (const float*)d_in[6];
    const int*   bidx   = (const int*)d_in[8];
    float* out = (float*)d_out;

    init_kernel<<<1, 32>>>();
    build_lists_kernel<<<1, 16>>>(bidx);

    // prep: per-box 1D gaussian tables (256 blocks, one per box)
    prep_kernel<<<NBOX, 128>>>(bboxes, 80, 0);
    prep_kernel<<<NBOX, 128>>>(bboxes, 40, 1);
    prep_kernel<<<NBOX, 128>>>(bboxes, 20, 2);

    // masks: totals 102400 / 25600 / 6400 elems, all divisible by 256
    mask_kernel<<<16 * PLANE0 / 256, 256>>>(80, 0, MOFF0);
    mask_kernel<<<16 * PLANE1 / 256, 256>>>(40, 1, MOFF1);
    mask_kernel<<<16 * PLANE2 / 256, 256>>>(20, 2, MOFF2);

    // reductions: threads = 16 * plane4 * nsplit; pick nsplit for ~205K threads
    {
        int plane4 = PLANE0 / 4, C = 128, cchunk = 16;  // nsplit=8
        int total = 16 * plane4 * (C / cchunk);          // 204800
        reduce_kernel<<<total / 256, 256>>>((const float4*)p0, (const float4*)t0,
                                            C, plane4, cchunk, 0, MOFF0);
    }
    {
        int plane4 = PLANE1 / 4, C = 256, cchunk = 8;   // nsplit=32
        int total = 16 * plane4 * (C / cchunk);          // 204800
        reduce_kernel<<<total / 256, 256>>>((const float4*)p1, (const float4*)t1,
                                            C, plane4, cchunk, 1, MOFF1);
    }
    {
        int plane4 = PLANE2 / 4, C = 512, cchunk = 4;   // nsplit=128
        int total = 16 * plane4 * (C / cchunk);          // 204800
        reduce_kernel<<<total / 256, 256>>>((const float4*)p2, (const float4*)t2,
                                            C, plane4, cchunk, 2, MOFF2);
    }

    final_kernel<<<1, 1>>>(out);
}

// round 6
// speedup vs baseline: 1.4471x; 1.4471x over previous
#include <cuda_runtime.h>
#include <math.h>

#define NBOX 256
#define BMAX 16

#define PLANE0 6400   // 80*80
#define PLANE1 1600   // 40*40
#define PLANE2 400    // 20*20
#define MOFF0 0
#define MOFF1 (16*PLANE0)            // 102400
#define MOFF2 (MOFF1 + 16*PLANE1)    // 128000
#define MTOT  (MOFF2 + 16*PLANE2)    // 134400

// block counts (256 threads each)
#define MBLK0 (16*PLANE0/256)   // 400
#define MBLK1 (16*PLANE1/256)   // 100
#define MBLK2 (16*PLANE2/256)   // 25
#define MBLK_TOT (MBLK0+MBLK1+MBLK2)  // 525

#define RBLK 800                // per level
#define RBLK_TOT (3*RBLK)       // 2400

// Scratch (allocation-free: __device__ globals)
__device__ __align__(16) float  g_ex[3][NBOX * 80];
__device__ __align__(16) float  g_ey[3][NBOX * 80];
__device__ __align__(16) float  g_mask[MTOT];
__device__ int    g_list[BMAX * NBOX];
__device__ int    g_cnt[BMAX];
__device__ double g_sse[3];
__device__ double g_summ[3];
__device__ int    g_done;

// ---------------------------------------------------------------------------
// Fused setup: blocks 0..767 build per-box separable gaussian tables
// (level = blk>>8, box = blk&255); block 768 does init + per-batch box lists.
// gauss = exp(-tx)*exp(-ty), denom = STD^2*(w/2)^2 = w^2 for STD=2.
__global__ void setup_kernel(const float* __restrict__ bboxes,
                             const int* __restrict__ bidx) {
    int blk = blockIdx.x;
    if (blk < 768) {
        int level = blk >> 8;
        int n = blk & 255;
        int S = (level == 0) ? 80 : (level == 1) ? 40 : 20;
        int x = threadIdx.x;
        if (x >= S) return;
        float4 bb = reinterpret_cast<const float4*>(bboxes)[n];
        float fS = (float)S;
        int S1 = S - 1;
        int xc = (int)floorf(bb.x * fS);
        int yc = (int)floorf(bb.y * fS);
        int w  = (int)floorf(bb.z * fS);
        int h  = (int)floorf(bb.w * fS);
        int xl = max(xc - w / 2, 0);
        int xr = min(xc + w / 2, S1);
        int yt = max(yc - h / 2, 0);
        int yd = min(yc + h / 2, S1);
        float wd = (float)(xr - xl + 1);
        float ht = (float)(yd - yt + 1);
        float fx = (float)x;
        float dx = fx - (float)xc;
        float dy = fx - (float)yc;
        float tx = (dx * dx) / (wd * wd);
        float ty = (dy * dy) / (ht * ht);
        g_ex[level][n * S + x] = (x >= xl && x <= xr) ? expf(-tx) : 0.0f;
        g_ey[level][n * S + x] = (x >= yt && x <= yd) ? expf(-ty) : 0.0f;
    } else {
        int t = threadIdx.x;
        if (t < 3) { g_sse[t] = 0.0; g_summ[t] = 0.0; }
        if (t == 20) g_done = 0;
        if (t < BMAX) {
            int c = 0;
            for (int n = 0; n < NBOX; n++)
                if (bidx[n] == t) g_list[t * NBOX + c++] = n;
            g_cnt[t] = c;
        }
    }
}

// ---------------------------------------------------------------------------
__device__ __forceinline__ float block_reduce_sum(float v) {
    __shared__ float sh[32];
    #pragma unroll
    for (int off = 16; off > 0; off >>= 1)
        v += __shfl_down_sync(0xffffffffu, v, off);
    int lane = threadIdx.x & 31;
    int wid  = threadIdx.x >> 5;
    if (lane == 0) sh[wid] = v;
    __syncthreads();
    v = (threadIdx.x < 8) ? sh[threadIdx.x] : 0.0f;
    if (wid == 0) {
        #pragma unroll
        for (int off = 4; off > 0; off >>= 1)
            v += __shfl_down_sync(0xffffffffu, v, off);
    }
    return v;  // valid in thread 0
}

// ---------------------------------------------------------------------------
template<int S, int MOFF, int LEVEL>
__device__ __forceinline__ void mask_body(int blk) {
    constexpr int plane = S * S;
    int i = blk * 256 + threadIdx.x;
    int b = i / plane;
    int r = i - b * plane;
    int y = r / S;
    int x = r - y * S;
    int cnt = g_cnt[b];
    const int*   lst = &g_list[b * NBOX];
    const float* ex  = g_ex[LEVEL];
    const float* ey  = g_ey[LEVEL];
    float v = 0.0f;
    for (int k = 0; k < cnt; k++) {
        int n = lst[k];
        v = fmaxf(v, ex[n * S + x] * ey[n * S + y]);
    }
    g_mask[MOFF + i] = v;
    float bs = block_reduce_sum(v);
    if (threadIdx.x == 0) atomicAdd(&g_summ[LEVEL], (double)bs);
}

// All 3 levels in one grid: [0,400) L0, [400,500) L1, [500,525) L2.
__global__ void mask_all_kernel() {
    int blk = blockIdx.x;
    if (blk < MBLK0)              mask_body<80, MOFF0, 0>(blk);
    else if (blk < MBLK0 + MBLK1) mask_body<40, MOFF1, 1>(blk - MBLK0);
    else                          mask_body<20, MOFF2, 2>(blk - MBLK0 - MBLK1);
}

// ---------------------------------------------------------------------------
// Main HBM-bound reduction. Each thread owns a fixed (b, j4) mask float4
// (register-resident) and streams CCHUNK channels of p/t.
template<int C, int CCHUNK, int PLANE4, int MOFF, int LEVEL>
__device__ __forceinline__ void reduce_body(const float4* __restrict__ p,
                                            const float4* __restrict__ t,
                                            int blk) {
    const float4* m = reinterpret_cast<const float4*>(&g_mask[MOFF]);
    constexpr int nsplit = C / CCHUNK;
    constexpr int per_b  = PLANE4 * nsplit;
    int idx = blk * 256 + threadIdx.x;
    int b  = idx / per_b;
    int r  = idx - b * per_b;
    int sp = r / PLANE4;
    int j  = r - sp * PLANE4;
    float4 mv = m[b * PLANE4 + j];
    int base = (b * C + sp * CCHUNK) * PLANE4 + j;
    float acc = 0.0f;
    #pragma unroll 8
    for (int c = 0; c < CCHUNK; c++) {
        float4 pv = p[base];
        float4 tv = t[base];
        base += PLANE4;
        float d0 = (pv.x - tv.x) * mv.x;
        float d1 = (pv.y - tv.y) * mv.y;
        float d2 = (pv.z - tv.z) * mv.z;
        float d3 = (pv.w - tv.w) * mv.w;
        acc += d0 * d0 + d1 * d1 + d2 * d2 + d3 * d3;
    }
    float bs = block_reduce_sum(acc);
    if (threadIdx.x == 0) atomicAdd(&g_sse[LEVEL], (double)bs);
}

// All 3 levels (800 blocks each) + fused epilogue in the last-finishing block.
__global__ void reduce_all_kernel(const float4* __restrict__ p0, const float4* __restrict__ t0,
                                  const float4* __restrict__ p1, const float4* __restrict__ t1,
                                  const float4* __restrict__ p2, const float4* __restrict__ t2,
                                  float* __restrict__ out) {
    int blk = blockIdx.x;
    if (blk < RBLK)            reduce_body<128, 16, PLANE0/4, MOFF0, 0>(p0, t0, blk);
    else if (blk < 2 * RBLK)   reduce_body<256,  8, PLANE1/4, MOFF1, 1>(p1, t1, blk - RBLK);
    else                       reduce_body<512,  4, PLANE2/4, MOFF2, 2>(p2, t2, blk - 2 * RBLK);

    if (threadIdx.x == 0) {
        __threadfence();
        int v = atomicAdd(&g_done, 1);
        if (v == RBLK_TOT - 1) {
            volatile double* sse  = g_sse;
            volatile double* summ = g_summ;
            double tot = sse[0] / (128.0 * summ[0])
                       + sse[1] / (256.0 * summ[1])
                       + sse[2] / (512.0 * summ[2]);
            out[0] = (float)(tot / 3.0);
        }
    }
}

// ---------------------------------------------------------------------------
extern "C" void kernel_launch(void* const* d_in, const int* in_sizes, int n_in,
                              void* d_out, int out_size) {
    // metadata order (interleaved): 0:y_pred0 1:y_true0 2:y_pred1 3:y_true1
    // 4:y_pred2 5:y_true2 6:bboxes 7:cls 8:batch_idx
    const float* p0 = (const float*)d_in[0];
    const float* t0 = (const float*)d_in[1];
    const float* p1 = (const float*)d_in[2];
    const float* t1 = (const float*)d_in[3];
    const float* p2 = (const float*)d_in[4];
    const float* t2 = (const float*)d_in[5];
    const float* bboxes = (const float*)d_in[6];
    const int*   bidx   = (const int*)d_in[8];
    float* out = (float*)d_out;

    setup_kernel<<<769, 128>>>(bboxes, bidx);
    mask_all_kernel<<<MBLK_TOT, 256>>>();
    reduce_all_kernel<<<RBLK_TOT, 256>>>((const float4*)p0, (const float4*)t0,
                                         (const float4*)p1, (const float4*)t1,
                                         (const float4*)p2, (const float4*)t2,
                                         out);
}

// round 8
// speedup vs baseline: 1.4545x; 1.0052x over previous
#include <cuda_runtime.h>
#include <math.h>

#define NBOX 256
#define BMAX 16

#define RBLK 800                // per level
#define RBLK_TOT (3*RBLK)       // 2400

// Scratch (allocation-free: __device__ globals)
__device__ __align__(16) float  g_ex[3][NBOX * 80];
__device__ __align__(16) float  g_ey[3][NBOX * 80];
__device__ int    g_list[BMAX * NBOX];
__device__ int    g_cnt[BMAX];
__device__ double g_sse[3];
__device__ double g_summ[3];
__device__ int    g_done;

// ---------------------------------------------------------------------------
// Fused setup: blocks 0..767 build per-box separable gaussian tables
// (level = blk>>8, box = blk&255); block 768 does init + PARALLEL per-batch
// box lists (order in g_list irrelevant: consumer takes max).
// gauss = exp(-tx)*exp(-ty), denom = STD^2*(w/2)^2 = w^2 for STD=2.
__global__ void setup_kernel(const float* __restrict__ bboxes,
                             const int* __restrict__ bidx) {
    int blk = blockIdx.x;
    if (blk < 768) {
        int level = blk >> 8;
        int n = blk & 255;
        int S = (level == 0) ? 80 : (level == 1) ? 40 : 20;
        int x = threadIdx.x;
        if (x >= S) return;
        float4 bb = reinterpret_cast<const float4*>(bboxes)[n];
        float fS = (float)S;
        int S1 = S - 1;
        int xc = (int)floorf(bb.x * fS);
        int yc = (int)floorf(bb.y * fS);
        int w  = (int)floorf(bb.z * fS);
        int h  = (int)floorf(bb.w * fS);
        int xl = max(xc - w / 2, 0);
        int xr = min(xc + w / 2, S1);
        int yt = max(yc - h / 2, 0);
        int yd = min(yc + h / 2, S1);
        float wd = (float)(xr - xl + 1);
        float ht = (float)(yd - yt + 1);
        float fx = (float)x;
        float dx = fx - (float)xc;
        float dy = fx - (float)yc;
        float tx = (dx * dx) / (wd * wd);
        float ty = (dy * dy) / (ht * ht);
        g_ex[level][n * S + x] = (x >= xl && x <= xr) ? expf(-tx) : 0.0f;
        g_ey[level][n * S + x] = (x >= yt && x <= yd) ? expf(-ty) : 0.0f;
    } else {
        int t = threadIdx.x;
        if (t < BMAX) g_cnt[t] = 0;
        if (t < 3) { g_sse[t] = 0.0; g_summ[t] = 0.0; }
        if (t == 20) g_done = 0;
        __syncthreads();
        // one thread per box: scatter into its batch's list
        int b = bidx[t];
        int slot = atomicAdd(&g_cnt[b], 1);
        g_list[b * NBOX + slot] = t;
    }
}

// ---------------------------------------------------------------------------
__device__ __forceinline__ float block_reduce_sum(float v, float* sh) {
    #pragma unroll
    for (int off = 16; off > 0; off >>= 1)
        v += __shfl_down_sync(0xffffffffu, v, off);
    int lane = threadIdx.x & 31;
    int wid  = threadIdx.x >> 5;
    if (lane == 0) sh[wid] = v;
    __syncthreads();
    v = (threadIdx.x < 8) ? sh[threadIdx.x] : 0.0f;
    if (wid == 0) {
        #pragma unroll
        for (int off = 4; off > 0; off >>= 1)
            v += __shfl_down_sync(0xffffffffu, v, off);
    }
    return v;  // valid in thread 0
}

// ---------------------------------------------------------------------------
// HBM-bound reduction with INLINE mask. Each thread owns a fixed (b, j4)
// float4 of pixels: builds the mask from the tiny 1-D tables (L1-resident),
// then streams CCHUNK channels of p/t.
template<int C, int CCHUNK, int S, int LEVEL>
__device__ __forceinline__ void reduce_body(const float4* __restrict__ p,
                                            const float4* __restrict__ t,
                                            int blk) {
    constexpr int PLANE4 = S * S / 4;
    constexpr int nsplit = C / CCHUNK;
    constexpr int per_b  = PLANE4 * nsplit;
    int idx = blk * 256 + threadIdx.x;
    int b  = idx / per_b;
    int r  = idx - b * per_b;
    int sp = r / PLANE4;
    int j  = r - sp * PLANE4;
    int pix = j * 4;
    int y   = pix / S;
    int x0  = pix - y * S;          // multiple of 4 (S % 4 == 0)

    // inline mask for pixels (y, x0..x0+3)
    int cnt = g_cnt[b];
    const int*   lst = &g_list[b * NBOX];
    const float* ex  = g_ex[LEVEL];
    const float* ey  = g_ey[LEVEL];
    float m0 = 0.0f, m1 = 0.0f, m2 = 0.0f, m3 = 0.0f;
    for (int k = 0; k < cnt; k++) {
        int n = lst[k];
        float4 exv = *reinterpret_cast<const float4*>(&ex[n * S + x0]);
        float  eyv = ey[n * S + y];
        m0 = fmaxf(m0, exv.x * eyv);
        m1 = fmaxf(m1, exv.y * eyv);
        m2 = fmaxf(m2, exv.z * eyv);
        m3 = fmaxf(m3, exv.w * eyv);
    }
    float sm = (m0 + m1 + m2 + m3) * (1.0f / (float)nsplit);

    int base = (b * C + sp * CCHUNK) * PLANE4 + j;
    float acc = 0.0f;
    #pragma unroll 8
    for (int c = 0; c < CCHUNK; c++) {
        float4 pv = p[base];
        float4 tv = t[base];
        base += PLANE4;
        float d0 = (pv.x - tv.x) * m0;
        float d1 = (pv.y - tv.y) * m1;
        float d2 = (pv.z - tv.z) * m2;
        float d3 = (pv.w - tv.w) * m3;
        acc += d0 * d0 + d1 * d1 + d2 * d2 + d3 * d3;
    }

    __shared__ float sh[32];
    float bs = block_reduce_sum(acc, sh);
    if (threadIdx.x == 0) atomicAdd(&g_sse[LEVEL], (double)bs);
    __syncthreads();
    float ms = block_reduce_sum(sm, sh);
    if (threadIdx.x == 0) atomicAdd(&g_summ[LEVEL], (double)ms);
}

// All 3 levels (800 blocks each) + fused epilogue in the last-finishing block.
__global__ void reduce_all_kernel(const float4* __restrict__ p0, const float4* __restrict__ t0,
                                  const float4* __restrict__ p1, const float4* __restrict__ t1,
                                  const float4* __restrict__ p2, const float4* __restrict__ t2,
                                  float* __restrict__ out) {
    int blk = blockIdx.x;
    if (blk < RBLK)            reduce_body<128, 16, 80, 0>(p0, t0, blk);
    else if (blk < 2 * RBLK)   reduce_body<256,  8, 40, 1>(p1, t1, blk - RBLK);
    else                       reduce_body<512,  4, 20, 2>(p2, t2, blk - 2 * RBLK);

    if (threadIdx.x == 0) {
        __threadfence();
        int v = atomicAdd(&g_done, 1);
        if (v == RBLK_TOT - 1) {
            volatile double* sse  = g_sse;
            volatile double* summ = g_summ;
            double tot = sse[0] / (128.0 * summ[0])
                       + sse[1] / (256.0 * summ[1])
                       + sse[2] / (512.0 * summ[2]);
            out[0] = (float)(tot / 3.0);
        }
    }
}

// ---------------------------------------------------------------------------
extern "C" void kernel_launch(void* const* d_in, const int* in_sizes, int n_in,
                              void* d_out, int out_size) {
    // metadata order (interleaved): 0:y_pred0 1:y_true0 2:y_pred1 3:y_true1
    // 4:y_pred2 5:y_true2 6:bboxes 7:cls 8:batch_idx
    const float* p0 = (const float*)d_in[0];
    const float* t0 = (const float*)d_in[1];
    const float* p1 = (const float*)d_in[2];
    const float* t1 = (const float*)d_in[3];
    const float* p2 = (const float*)d_in[4];
    const float* t2 = (const float*)d_in[5];
    const float* bboxes = (const float*)d_in[6];
    const int*   bidx   = (const int*)d_in[8];
    float* out = (float*)d_out;

    setup_kernel<<<769, 256>>>(bboxes, bidx);
    reduce_all_kernel<<<RBLK_TOT, 256>>>((const float4*)p0, (const float4*)t0,
                                         (const float4*)p1, (const float4*)t1,
                                         (const float4*)p2, (const float4*)t2,
                                         out);
}

// round 9
// speedup vs baseline: 1.7421x; 1.1977x over previous
#include <cuda_runtime.h>
#include <math.h>

#define NBOX 256
#define BMAX 16

// equal work per block: every thread streams CCHUNK=16 float4 pairs (512B)
#define RBLK0 800
#define RBLK1 400
#define RBLK2 200
#define RBLK_TOT (RBLK0 + RBLK1 + RBLK2)   // 1400

// Scratch (allocation-free: __device__ globals)
__device__ __align__(16) float  g_ex[3][NBOX * 80];
__device__ __align__(16) float  g_ey[3][NBOX * 80];
__device__ int    g_list[BMAX * NBOX];
__device__ int    g_cnt[BMAX];
__device__ double g_sse[3];
__device__ double g_summ[3];
__device__ int    g_done;

// ---------------------------------------------------------------------------
// Fused setup: blocks 0..767 build per-box separable gaussian tables
// (level = blk>>8, box = blk&255); block 768 does init + parallel per-batch
// box lists (order in g_list irrelevant: consumer takes max).
// gauss = exp(-tx)*exp(-ty), denom = STD^2*(w/2)^2 = w^2 for STD=2.
__global__ void setup_kernel(const float* __restrict__ bboxes,
                             const int* __restrict__ bidx) {
    int blk = blockIdx.x;
    if (blk < 768) {
        int level = blk >> 8;
        int n = blk & 255;
        int S = (level == 0) ? 80 : (level == 1) ? 40 : 20;
        int x = threadIdx.x;
        if (x >= S) return;
        float4 bb = reinterpret_cast<const float4*>(bboxes)[n];
        float fS = (float)S;
        int S1 = S - 1;
        int xc = (int)floorf(bb.x * fS);
        int yc = (int)floorf(bb.y * fS);
        int w  = (int)floorf(bb.z * fS);
        int h  = (int)floorf(bb.w * fS);
        int xl = max(xc - w / 2, 0);
        int xr = min(xc + w / 2, S1);
        int yt = max(yc - h / 2, 0);
        int yd = min(yc + h / 2, S1);
        float wd = (float)(xr - xl + 1);
        float ht = (float)(yd - yt + 1);
        float fx = (float)x;
        float dx = fx - (float)xc;
        float dy = fx - (float)yc;
        float tx = (dx * dx) / (wd * wd);
        float ty = (dy * dy) / (ht * ht);
        g_ex[level][n * S + x] = (x >= xl && x <= xr) ? expf(-tx) : 0.0f;
        g_ey[level][n * S + x] = (x >= yt && x <= yd) ? expf(-ty) : 0.0f;
    } else {
        int t = threadIdx.x;
        if (t < BMAX) g_cnt[t] = 0;
        if (t < 3) { g_sse[t] = 0.0; g_summ[t] = 0.0; }
        if (t == 20) g_done = 0;
        __syncthreads();
        // one thread per box: scatter into its batch's list
        int b = bidx[t];
        int slot = atomicAdd(&g_cnt[b], 1);
        g_list[b * NBOX + slot] = t;
    }
}

// ---------------------------------------------------------------------------
// dual block reduction (one shared pass, one __syncthreads)
__device__ __forceinline__ void block_reduce_sum2(float& a, float& b) {
    __shared__ float sha[8], shb[8];
    #pragma unroll
    for (int off = 16; off > 0; off >>= 1) {
        a += __shfl_down_sync(0xffffffffu, a, off);
        b += __shfl_down_sync(0xffffffffu, b, off);
    }
    int lane = threadIdx.x & 31;
    int wid  = threadIdx.x >> 5;
    if (lane == 0) { sha[wid] = a; shb[wid] = b; }
    __syncthreads();
    if (wid == 0) {
        a = (lane < 8) ? sha[lane] : 0.0f;
        b = (lane < 8) ? shb[lane] : 0.0f;
        #pragma unroll
        for (int off = 4; off > 0; off >>= 1) {
            a += __shfl_down_sync(0xffffffffu, a, off);
            b += __shfl_down_sync(0xffffffffu, b, off);
        }
    }
}

// ---------------------------------------------------------------------------
// HBM-bound reduction with inline mask. Each thread owns a fixed (b, j4)
// float4 of pixels and streams CCHUNK=16 channels of p/t with explicit
// batch-of-4 pair loads (8 LDG.128 outstanding), __ldcs (read-once).
#define CCHUNK 16
template<int C, int S, int LEVEL>
__device__ __forceinline__ void reduce_body(const float4* __restrict__ p,
                                            const float4* __restrict__ t,
                                            int blk) {
    constexpr int PLANE4 = S * S / 4;
    constexpr int nsplit = C / CCHUNK;
    constexpr int per_b  = PLANE4 * nsplit;
    int idx = blk * 256 + threadIdx.x;
    int b  = idx / per_b;
    int r  = idx - b * per_b;
    int sp = r / PLANE4;
    int j  = r - sp * PLANE4;
    int pix = j * 4;
    int y   = pix / S;
    int x0  = pix - y * S;          // multiple of 4 (S % 4 == 0)

    int base = (b * C + sp * CCHUNK) * PLANE4 + j;

    // issue first load batch (stays in flight during mask computation)
    float4 pv[4], tv[4];
    #pragma unroll
    for (int u = 0; u < 4; u++) pv[u] = __ldcs(p + base + u * PLANE4);
    #pragma unroll
    for (int u = 0; u < 4; u++) tv[u] = __ldcs(t + base + u * PLANE4);

    // inline mask for pixels (y, x0..x0+3) from tiny L1-resident tables
    int cnt = g_cnt[b];
    const int*   lst = &g_list[b * NBOX];
    const float* ex  = g_ex[LEVEL];
    const float* ey  = g_ey[LEVEL];
    float m0 = 0.0f, m1 = 0.0f, m2 = 0.0f, m3 = 0.0f;
    for (int k = 0; k < cnt; k++) {
        int n = lst[k];
        float4 exv = *reinterpret_cast<const float4*>(&ex[n * S + x0]);
        float  eyv = ey[n * S + y];
        m0 = fmaxf(m0, exv.x * eyv);
        m1 = fmaxf(m1, exv.y * eyv);
        m2 = fmaxf(m2, exv.z * eyv);
        m3 = fmaxf(m3, exv.w * eyv);
    }
    float sm = (m0 + m1 + m2 + m3) * (1.0f / (float)nsplit);

    float acc0 = 0.0f, acc1 = 0.0f;
    #pragma unroll
    for (int cc = 0; cc < CCHUNK; cc += 4) {
        if (cc > 0) {
            base += 4 * PLANE4;
            #pragma unroll
            for (int u = 0; u < 4; u++) pv[u] = __ldcs(p + base + u * PLANE4);
            #pragma unroll
            for (int u = 0; u < 4; u++) tv[u] = __ldcs(t + base + u * PLANE4);
        }
        #pragma unroll
        for (int u = 0; u < 4; u++) {
            float d0 = (pv[u].x - tv[u].x) * m0;
            float d1 = (pv[u].y - tv[u].y) * m1;
            float d2 = (pv[u].z - tv[u].z) * m2;
            float d3 = (pv[u].w - tv[u].w) * m3;
            acc0 += d0 * d0 + d1 * d1;
            acc1 += d2 * d2 + d3 * d3;
        }
    }

    float acc = acc0 + acc1;
    block_reduce_sum2(acc, sm);
    if (threadIdx.x == 0) {
        atomicAdd(&g_sse[LEVEL],  (double)acc);
        atomicAdd(&g_summ[LEVEL], (double)sm);
    }
}

// Levels packed by traffic share: [0,800) L0, [800,1200) L1, [1200,1400) L2.
// Fused epilogue in the last-finishing block via done-counter.
__global__ void reduce_all_kernel(const float4* __restrict__ p0, const float4* __restrict__ t0,
                                  const float4* __restrict__ p1, const float4* __restrict__ t1,
                                  const float4* __restrict__ p2, const float4* __restrict__ t2,
                                  float* __restrict__ out) {
    int blk = blockIdx.x;
    if (blk < RBLK0)               reduce_body<128, 80, 0>(p0, t0, blk);
    else if (blk < RBLK0 + RBLK1)  reduce_body<256, 40, 1>(p1, t1, blk - RBLK0);
    else                           reduce_body<512, 20, 2>(p2, t2, blk - RBLK0 - RBLK1);

    if (threadIdx.x == 0) {
        __threadfence();
        int v = atomicAdd(&g_done, 1);
        if (v == RBLK_TOT - 1) {
            volatile double* sse  = g_sse;
            volatile double* summ = g_summ;
            double tot = sse[0] / (128.0 * summ[0])
                       + sse[1] / (256.0 * summ[1])
                       + sse[2] / (512.0 * summ[2]);
            out[0] = (float)(tot / 3.0);
        }
    }
}

// ---------------------------------------------------------------------------
extern "C" void kernel_launch(void* const* d_in, const int* in_sizes, int n_in,
                              void* d_out, int out_size) {
    // metadata order (interleaved): 0:y_pred0 1:y_true0 2:y_pred1 3:y_true1
    // 4:y_pred2 5:y_true2 6:bboxes 7:cls 8:batch_idx
    const float* p0 = (const float*)d_in[0];
    const float* t0 = (const float*)d_in[1];
    const float* p1 = (const float*)d_in[2];
    const float* t1 = (const float*)d_in[3];
    const float* p2 = (const float*)d_in[4];
    const float* t2 = (const float*)d_in[5];
    const float* bboxes = (const float*)d_in[6];
    const int*   bidx   = (const int*)d_in[8];
    float* out = (float*)d_out;

    setup_kernel<<<769, 256>>>(bboxes, bidx);
    reduce_all_kernel<<<RBLK_TOT, 256>>>((const float4*)p0, (const float4*)t0,
                                         (const float4*)p1, (const float4*)t1,
                                         (const float4*)p2, (const float4*)t2,
                                         out);
}